// round 8
// baseline (speedup 1.0000x reference)
#include <cuda_runtime.h>
#include <math.h>

#define ALPHA 0.7f
#define EPS 1e-7f

#define NBLOCKS 1152        // 1152*256 = 294,912 threads; n4 / 294,912 = 24 exactly
#define NTHREADS 256

__device__ float g_partials[NBLOCKS];
__device__ unsigned int g_ticket;   // zero at load; last block resets each call

__device__ __forceinline__ float focal_quad(float4 p, int4 y) {
    float s = 0.0f;
    {
        bool pos = (y.x == 1);
        float c  = 1.0f - p.x;
        float pt = pos ? p.x : c;    // pt
        float om = pos ? c : p.x;    // 1 - pt
        float l  = -__logf(pt);
        if (isinf(l)) l = EPS;
        float f  = om * om * l;
        s += pos ? f * ALPHA : f;
    }
    {
        bool pos = (y.y == 1);
        float c  = 1.0f - p.y;
        float pt = pos ? p.y : c;
        float om = pos ? c : p.y;
        float l  = -__logf(pt);
        if (isinf(l)) l = EPS;
        float f  = om * om * l;
        s += pos ? f * ALPHA : f;
    }
    {
        bool pos = (y.z == 1);
        float c  = 1.0f - p.z;
        float pt = pos ? p.z : c;
        float om = pos ? c : p.z;
        float l  = -__logf(pt);
        if (isinf(l)) l = EPS;
        float f  = om * om * l;
        s += pos ? f * ALPHA : f;
    }
    {
        bool pos = (y.w == 1);
        float c  = 1.0f - p.w;
        float pt = pos ? p.w : c;
        float om = pos ? c : p.w;
        float l  = -__logf(pt);
        if (isinf(l)) l = EPS;
        float f  = om * om * l;
        s += pos ? f * ALPHA : f;
    }
    return s;
}

__global__ void __launch_bounds__(NTHREADS, 6) focal_fused_kernel(
    const float* __restrict__ p_in,
    const int*   __restrict__ y_in,
    unsigned int n4,       // number of float4 quads
    long long n,           // total elements
    float* __restrict__ out)
{
    const float4* __restrict__ p4 = (const float4*)p_in;
    const int4*   __restrict__ y4 = (const int4*)y_in;

    float acc = 0.0f;

    const unsigned int idx    = blockIdx.x * (unsigned int)NTHREADS + threadIdx.x;
    const unsigned int stride = gridDim.x * (unsigned int)NTHREADS;
    const unsigned int iters  = n4 / stride;   // uniform: 24 for the bench shape

    unsigned int i = idx;

    if (iters >= 2) {
        // prime two stages
        float4 pa = p4[i];
        int4   ya = y4[i];
        float4 pb = p4[i + stride];
        int4   yb = y4[i + stride];

        // depth-2 rotation: always 2 iterations of loads in flight
        unsigned int it = 2;
        for (; it < iters; ++it) {
            unsigned int inext = i + 2u * stride;
            float4 pn = p4[inext];
            int4   yn = y4[inext];
            acc += focal_quad(pa, ya);
            pa = pb; ya = yb;
            pb = pn; yb = yn;
            i += stride;
        }
        acc += focal_quad(pa, ya);
        acc += focal_quad(pb, yb);
        i += 2u * stride;
    } else if (iters == 1) {
        acc += focal_quad(p4[i], y4[i]);
        i += stride;
    }
    // tail (zero iterations for the bench shape, kept for generality)
    if (i < n4) {
        acc += focal_quad(p4[i], y4[i]);
    }

    // ---- intra-block reduction ----
    #pragma unroll
    for (int off = 16; off > 0; off >>= 1)
        acc += __shfl_xor_sync(0xFFFFFFFFu, acc, off);

    __shared__ float warp_sums[NTHREADS / 32];
    __shared__ bool  s_is_last;
    int lane = threadIdx.x & 31;
    int wid  = threadIdx.x >> 5;
    if (lane == 0) warp_sums[wid] = acc;
    __syncthreads();

    if (threadIdx.x == 0) {
        float bs = 0.0f;
        #pragma unroll
        for (int w = 0; w < NTHREADS / 32; w++) bs += warp_sums[w];
        g_partials[blockIdx.x] = bs;
        __threadfence();
        unsigned int t = atomicAdd(&g_ticket, 1u);
        s_is_last = (t == gridDim.x - 1);
    }
    __syncthreads();

    // ---- last block performs the final reduction ----
    if (s_is_last) {
        float v = 0.0f;
        for (unsigned int j = threadIdx.x; j < gridDim.x; j += NTHREADS)
            v += g_partials[j];

        #pragma unroll
        for (int off = 16; off > 0; off >>= 1)
            v += __shfl_xor_sync(0xFFFFFFFFu, v, off);

        if (lane == 0) warp_sums[wid] = v;
        __syncthreads();

        if (threadIdx.x == 0) {
            float total = 0.0f;
            #pragma unroll
            for (int w = 0; w < NTHREADS / 32; w++) total += warp_sums[w];
            out[0] = (float)((double)total / (double)n);
            g_ticket = 0;   // reset for next graph replay
        }
    }
}

extern "C" void kernel_launch(void* const* d_in, const int* in_sizes, int n_in,
                              void* d_out, int out_size) {
    const float* p = (const float*)d_in[0];
    const int*   y = (const int*)d_in[1];
    float* out = (float*)d_out;

    long long n  = (long long)in_sizes[0];
    unsigned int n4 = (unsigned int)(n / 4);   // 7,077,888 quads

    int blocks = NBLOCKS;
    long long needed = ((long long)n4 + NTHREADS - 1) / NTHREADS;
    if ((long long)blocks > needed) blocks = (int)needed;

    focal_fused_kernel<<<blocks, NTHREADS>>>(p, y, n4, n, out);
}

// round 9
// speedup vs baseline: 1.1235x; 1.1235x over previous
#include <cuda_runtime.h>
#include <math.h>

#define ALPHA 0.7f
#define EPS 1e-7f

#define NBLOCKS 1024        // 27,648 tiles / 1024 = 27 tiles per block exactly
#define NTHREADS 256
#define NSTAGES 4

__device__ float g_partials[NBLOCKS];
__device__ unsigned int g_ticket;   // zero at load; last block resets each call

__device__ __forceinline__ void cp16(void* smem_dst, const void* gsrc, bool pred) {
    unsigned int saddr = (unsigned int)__cvta_generic_to_shared(smem_dst);
    if (pred) {
        asm volatile("cp.async.cg.shared.global [%0], [%1], 16;\n"
                     :: "r"(saddr), "l"(gsrc));
    } else {
        asm volatile("st.shared.v4.b32 [%0], {%1,%1,%1,%1};\n"
                     :: "r"(saddr), "r"(0));   // zero quad contributes 0 to the sum
    }
}

__device__ __forceinline__ float focal_quad(float4 p, int4 y) {
    float s = 0.0f;
    {
        bool pos = (y.x == 1);
        float c  = 1.0f - p.x;
        float pt = pos ? p.x : c;
        float om = pos ? c : p.x;
        float l  = -__logf(pt);
        if (isinf(l)) l = EPS;
        float f  = om * om * l;
        s += pos ? f * ALPHA : f;
    }
    {
        bool pos = (y.y == 1);
        float c  = 1.0f - p.y;
        float pt = pos ? p.y : c;
        float om = pos ? c : p.y;
        float l  = -__logf(pt);
        if (isinf(l)) l = EPS;
        float f  = om * om * l;
        s += pos ? f * ALPHA : f;
    }
    {
        bool pos = (y.z == 1);
        float c  = 1.0f - p.z;
        float pt = pos ? p.z : c;
        float om = pos ? c : p.z;
        float l  = -__logf(pt);
        if (isinf(l)) l = EPS;
        float f  = om * om * l;
        s += pos ? f * ALPHA : f;
    }
    {
        bool pos = (y.w == 1);
        float c  = 1.0f - p.w;
        float pt = pos ? p.w : c;
        float om = pos ? c : p.w;
        float l  = -__logf(pt);
        if (isinf(l)) l = EPS;
        float f  = om * om * l;
        s += pos ? f * ALPHA : f;
    }
    return s;
}

__global__ void __launch_bounds__(NTHREADS) focal_fused_kernel(
    const float* __restrict__ p_in,
    const int*   __restrict__ y_in,
    unsigned int n4,       // number of float4 quads
    long long n,           // total elements
    float* __restrict__ out)
{
    __shared__ float4 sp[NSTAGES][NTHREADS];
    __shared__ int4   sy[NSTAGES][NTHREADS];

    const float4* __restrict__ p4 = (const float4*)p_in;
    const int4*   __restrict__ y4 = (const int4*)y_in;

    const unsigned int tid  = threadIdx.x;
    const unsigned int grid = gridDim.x;
    const unsigned int ntiles = (n4 + NTHREADS - 1) / NTHREADS;
    const unsigned int iters  = (ntiles + grid - 1) / grid;   // uniform (27 on bench shape)

    float acc = 0.0f;

    // ---- prologue: prefetch NSTAGES-1 tiles ----
    #pragma unroll
    for (unsigned int s = 0; s < NSTAGES - 1; ++s) {
        unsigned int tile = blockIdx.x + s * grid;
        unsigned int q = tile * NTHREADS + tid;
        bool ok = (tile < ntiles) && (q < n4);
        cp16(&sp[s][tid], p4 + q, ok);
        cp16(&sy[s][tid], y4 + q, ok);
        asm volatile("cp.async.commit_group;\n");
    }

    // ---- steady state: each thread consumes only data it copied itself,
    //      so no __syncthreads needed; wait_group is per-thread. ----
    for (unsigned int t = 0; t < iters; ++t) {
        {   // issue tile t + NSTAGES-1 into its stage
            unsigned int tf = t + NSTAGES - 1;
            unsigned int stage = tf % NSTAGES;
            unsigned int tile = blockIdx.x + tf * grid;
            unsigned int q = tile * NTHREADS + tid;
            bool ok = (tf < iters) && (tile < ntiles) && (q < n4);
            cp16(&sp[stage][tid], p4 + q, ok);
            cp16(&sy[stage][tid], y4 + q, ok);
            asm volatile("cp.async.commit_group;\n");
        }
        // allow newest NSTAGES-1 groups in flight; oldest (tile t) is complete
        asm volatile("cp.async.wait_group %0;\n" :: "n"(NSTAGES - 1));

        unsigned int stage = t % NSTAGES;
        float4 p = sp[stage][tid];
        int4   y = sy[stage][tid];
        acc += focal_quad(p, y);
    }
    asm volatile("cp.async.wait_group 0;\n");

    // ---- intra-block reduction ----
    #pragma unroll
    for (int off = 16; off > 0; off >>= 1)
        acc += __shfl_xor_sync(0xFFFFFFFFu, acc, off);

    __shared__ float warp_sums[NTHREADS / 32];
    __shared__ bool  s_is_last;
    int lane = threadIdx.x & 31;
    int wid  = threadIdx.x >> 5;
    if (lane == 0) warp_sums[wid] = acc;
    __syncthreads();

    if (threadIdx.x == 0) {
        float bs = 0.0f;
        #pragma unroll
        for (int w = 0; w < NTHREADS / 32; w++) bs += warp_sums[w];
        g_partials[blockIdx.x] = bs;
        __threadfence();
        unsigned int t = atomicAdd(&g_ticket, 1u);
        s_is_last = (t == gridDim.x - 1);
    }
    __syncthreads();

    // ---- last block performs the final reduction ----
    if (s_is_last) {
        float v = 0.0f;
        for (unsigned int j = threadIdx.x; j < gridDim.x; j += NTHREADS)
            v += g_partials[j];

        #pragma unroll
        for (int off = 16; off > 0; off >>= 1)
            v += __shfl_xor_sync(0xFFFFFFFFu, v, off);

        if (lane == 0) warp_sums[wid] = v;
        __syncthreads();

        if (threadIdx.x == 0) {
            float total = 0.0f;
            #pragma unroll
            for (int w = 0; w < NTHREADS / 32; w++) total += warp_sums[w];
            out[0] = (float)((double)total / (double)n);
            g_ticket = 0;   // reset for next graph replay
        }
    }
}

extern "C" void kernel_launch(void* const* d_in, const int* in_sizes, int n_in,
                              void* d_out, int out_size) {
    const float* p = (const float*)d_in[0];
    const int*   y = (const int*)d_in[1];
    float* out = (float*)d_out;

    long long n  = (long long)in_sizes[0];
    unsigned int n4 = (unsigned int)(n / 4);   // 7,077,888 quads

    focal_fused_kernel<<<NBLOCKS, NTHREADS>>>(p, y, n4, n, out);
}

// round 13
// speedup vs baseline: 1.2496x; 1.1122x over previous
#include <cuda_runtime.h>
#include <math.h>

#define ALPHA 0.7f
#define EPS 1e-7f

#define NBLOCKS 1152        // 1152*256 = 294,912 threads; n4 / 294,912 = 24 exactly
#define NTHREADS 256

__device__ float g_partials[NBLOCKS];
__device__ unsigned int g_ticket;   // zero at load; last block resets each call

__device__ __forceinline__ float focal_quad(float4 p, int4 y) {
    float s = 0.0f;
    {
        bool pos = (y.x == 1);
        float c  = 1.0f - p.x;
        float pt = pos ? p.x : c;    // pt
        float om = pos ? c : p.x;    // 1 - pt
        float l  = -__logf(pt);
        if (isinf(l)) l = EPS;
        float f  = om * om * l;
        s += pos ? f * ALPHA : f;
    }
    {
        bool pos = (y.y == 1);
        float c  = 1.0f - p.y;
        float pt = pos ? p.y : c;
        float om = pos ? c : p.y;
        float l  = -__logf(pt);
        if (isinf(l)) l = EPS;
        float f  = om * om * l;
        s += pos ? f * ALPHA : f;
    }
    {
        bool pos = (y.z == 1);
        float c  = 1.0f - p.z;
        float pt = pos ? p.z : c;
        float om = pos ? c : p.z;
        float l  = -__logf(pt);
        if (isinf(l)) l = EPS;
        float f  = om * om * l;
        s += pos ? f * ALPHA : f;
    }
    {
        bool pos = (y.w == 1);
        float c  = 1.0f - p.w;
        float pt = pos ? p.w : c;
        float om = pos ? c : p.w;
        float l  = -__logf(pt);
        if (isinf(l)) l = EPS;
        float f  = om * om * l;
        s += pos ? f * ALPHA : f;
    }
    return s;
}

__global__ void __launch_bounds__(NTHREADS) focal_fused_kernel(
    const float* __restrict__ p_in,
    const int*   __restrict__ y_in,
    unsigned int n4,       // number of float4 quads
    long long n,           // total elements
    float* __restrict__ out)
{
    const float4* __restrict__ p4 = (const float4*)p_in;
    const int4*   __restrict__ y4 = (const int4*)y_in;

    float acc = 0.0f;

    const unsigned int idx    = blockIdx.x * (unsigned int)NTHREADS + threadIdx.x;
    const unsigned int stride = gridDim.x * (unsigned int)NTHREADS;
    const unsigned int iters  = n4 / stride;   // uniform: 24 for the bench shape

    unsigned int i = idx;

    if (iters > 0) {
        // prime the pipeline
        float4 p = p4[i];
        int4   y = y4[i];

        // depth-1 prefetch: issue next loads before consuming current regs
        for (unsigned int it = 1; it < iters; ++it) {
            unsigned int inext = i + stride;
            float4 pn = p4[inext];
            int4   yn = y4[inext];
            acc += focal_quad(p, y);
            p = pn; y = yn; i = inext;
        }
        acc += focal_quad(p, y);
        i += stride;
    }
    // tail (zero iterations for the bench shape, kept for generality)
    if (i < n4) {
        acc += focal_quad(p4[i], y4[i]);
    }

    // ---- intra-block reduction ----
    #pragma unroll
    for (int off = 16; off > 0; off >>= 1)
        acc += __shfl_xor_sync(0xFFFFFFFFu, acc, off);

    __shared__ float warp_sums[NTHREADS / 32];
    __shared__ bool  s_is_last;
    int lane = threadIdx.x & 31;
    int wid  = threadIdx.x >> 5;
    if (lane == 0) warp_sums[wid] = acc;
    __syncthreads();

    if (threadIdx.x == 0) {
        float bs = 0.0f;
        #pragma unroll
        for (int w = 0; w < NTHREADS / 32; w++) bs += warp_sums[w];
        g_partials[blockIdx.x] = bs;
        __threadfence();
        unsigned int t = atomicAdd(&g_ticket, 1u);
        s_is_last = (t == gridDim.x - 1);
    }
    __syncthreads();

    // ---- last block performs the final reduction ----
    if (s_is_last) {
        float v = 0.0f;
        for (unsigned int j = threadIdx.x; j < gridDim.x; j += NTHREADS)
            v += g_partials[j];

        #pragma unroll
        for (int off = 16; off > 0; off >>= 1)
            v += __shfl_xor_sync(0xFFFFFFFFu, v, off);

        if (lane == 0) warp_sums[wid] = v;
        __syncthreads();

        if (threadIdx.x == 0) {
            float total = 0.0f;
            #pragma unroll
            for (int w = 0; w < NTHREADS / 32; w++) total += warp_sums[w];
            out[0] = (float)((double)total / (double)n);
            g_ticket = 0;   // reset for next graph replay
        }
    }
}

extern "C" void kernel_launch(void* const* d_in, const int* in_sizes, int n_in,
                              void* d_out, int out_size) {
    const float* p = (const float*)d_in[0];
    const int*   y = (const int*)d_in[1];
    float* out = (float*)d_out;

    long long n  = (long long)in_sizes[0];
    unsigned int n4 = (unsigned int)(n / 4);   // 7,077,888 quads

    int blocks = NBLOCKS;
    long long needed = ((long long)n4 + NTHREADS - 1) / NTHREADS;
    if ((long long)blocks > needed) blocks = (int)needed;

    focal_fused_kernel<<<blocks, NTHREADS>>>(p, y, n4, n, out);
}